// round 1
// baseline (speedup 1.0000x reference)
#include <cuda_runtime.h>
#include <math.h>

#define T_    512
#define H_    1024
#define HD_   64
#define NQ_   16
#define NKV_  4
#define G_    4
#define E_    8
#define FFN_  1024
#define B_    4
#define Q_    128
#define P_    8
#define PS_   128
#define S_    1024
#define SW_   128
#define QKVD  1536          // HD*(NQ+2*NKV)
#define SCALE_ 0.125f       // HD^-0.5
#define ALPHA_ 1.702f
#define LIMIT_ 7.0f
#define EPS_   1e-5f

// ---------------- scratch (no allocation allowed) ----------------
__device__ float g_x[T_ * H_];
__device__ float g_qkv[T_ * QKVD];
__device__ float g_attn[T_ * NQ_ * HD_];
__device__ float g_x2[T_ * H_];
__device__ int   g_eidx[T_ * 2];
__device__ float g_ewt[T_ * 2];

// ---------------- rmsnorm ----------------
__global__ void rmsnorm_kernel(const float* __restrict__ in,
                               const float* __restrict__ w,
                               float* __restrict__ out) {
    int t = blockIdx.x;
    const float* x = in + (size_t)t * H_;
    __shared__ float red[256];
    float ss = 0.f;
    for (int i = threadIdx.x; i < H_; i += 256) { float v = x[i]; ss += v * v; }
    red[threadIdx.x] = ss; __syncthreads();
    for (int s = 128; s > 0; s >>= 1) {
        if (threadIdx.x < s) red[threadIdx.x] += red[threadIdx.x + s];
        __syncthreads();
    }
    float r = rsqrtf(red[0] / (float)H_ + EPS_);
    for (int i = threadIdx.x; i < H_; i += 256)
        out[(size_t)t * H_ + i] = x[i] * w[i] * r;
}

// ---------------- 64x64 register-tiled SGEMM, C = A@B + bias (+res) ----------------
template<bool RES>
__global__ void sgemm64(const float* __restrict__ A, const float* __restrict__ B,
                        const float* __restrict__ bias, const float* __restrict__ res,
                        float* __restrict__ C, int M, int N, int K) {
    __shared__ float As[16][64];
    __shared__ float Bs[16][64];
    int tid = threadIdx.x;
    int tx = tid % 16, ty = tid / 16;
    int m0 = blockIdx.y * 64, n0 = blockIdx.x * 64;
    int arow = tid >> 2, ac4 = tid & 3;     // A tile: 64 rows x 16 cols, float4 each
    int brow = tid >> 4, bc4 = tid & 15;    // B tile: 16 rows x 64 cols, float4 each
    float acc[4][4] = {};
    for (int k0 = 0; k0 < K; k0 += 16) {
        float4 av = *(const float4*)&A[(size_t)(m0 + arow) * K + k0 + ac4 * 4];
        As[ac4 * 4 + 0][arow] = av.x;
        As[ac4 * 4 + 1][arow] = av.y;
        As[ac4 * 4 + 2][arow] = av.z;
        As[ac4 * 4 + 3][arow] = av.w;
        float4 bv = *(const float4*)&B[(size_t)(k0 + brow) * N + n0 + bc4 * 4];
        *(float4*)&Bs[brow][bc4 * 4] = bv;
        __syncthreads();
        #pragma unroll
        for (int k = 0; k < 16; k++) {
            float a[4], b[4];
            #pragma unroll
            for (int i = 0; i < 4; i++) a[i] = As[k][ty * 4 + i];
            #pragma unroll
            for (int j = 0; j < 4; j++) b[j] = Bs[k][tx * 4 + j];
            #pragma unroll
            for (int i = 0; i < 4; i++)
                #pragma unroll
                for (int j = 0; j < 4; j++)
                    acc[i][j] += a[i] * b[j];
        }
        __syncthreads();
    }
    #pragma unroll
    for (int i = 0; i < 4; i++) {
        int row = m0 + ty * 4 + i;
        #pragma unroll
        for (int j = 0; j < 4; j++) {
            int col = n0 + tx * 4 + j;
            float v = acc[i][j] + bias[col];
            if (RES) v += res[(size_t)row * N + col];
            C[(size_t)row * N + col] = v;
        }
    }
}

// ---------------- sliding-window attention with sink ----------------
// grid (NQ, Q, B), 128 threads. Each query attends to exactly 128 keys
// [qpos-127, qpos] (window subset of causal; mask there is 0 but we add it).
__global__ void attn_kernel(const float* __restrict__ qkv,
                            const float* __restrict__ kvc,
                            const int* __restrict__ pidx,
                            const float* __restrict__ mask,
                            const float* __restrict__ sinks,
                            float* __restrict__ attn) {
    int h = blockIdx.x, q = blockIdx.y, b = blockIdx.z;
    int t = b * Q_ + q;
    int qpos = S_ - Q_ + q;
    int kv = h / G_;
    int tid = threadIdx.x;

    __shared__ float qs[HD_];
    __shared__ float sc[SW_];
    __shared__ float red[SW_];
    __shared__ float vr[2][HD_];

    if (tid < HD_) qs[tid] = qkv[(size_t)t * QKVD + h * HD_ + tid] * SCALE_;
    __syncthreads();

    // scores: one key per thread
    int kpos = qpos - (SW_ - 1) + tid;
    const float* kp;
    if (kpos < S_ - Q_) {
        int page = pidx[b * P_ + kpos / PS_];
        kp = kvc + ((((size_t)page * 2 + 0) * PS_ + (kpos % PS_)) * NKV_ + kv) * HD_;
    } else {
        kp = qkv + (size_t)(b * Q_ + kpos - (S_ - Q_)) * QKVD + NQ_ * HD_ + kv * HD_;
    }
    float s = 0.f;
    #pragma unroll
    for (int d = 0; d < HD_; d++) s += qs[d] * kp[d];
    s += mask[((size_t)b * Q_ + q) * S_ + kpos];
    sc[tid] = s;
    red[tid] = s;
    __syncthreads();
    for (int st = 64; st > 0; st >>= 1) {
        if (tid < st) red[tid] = fmaxf(red[tid], red[tid + st]);
        __syncthreads();
    }
    float m = red[0];
    __syncthreads();
    float p = expf(s - m);
    sc[tid] = p;
    red[tid] = p;
    __syncthreads();
    for (int st = 64; st > 0; st >>= 1) {
        if (tid < st) red[tid] += red[tid + st];
        __syncthreads();
    }
    float denom = red[0] + expf(sinks[h] - m);

    // attn @ V : 2 halves of the window, 64 dims each
    int half = tid >> 6;
    int d = tid & 63;
    float acc = 0.f;
    for (int jj = half * 64; jj < half * 64 + 64; jj++) {
        int kp2 = qpos - (SW_ - 1) + jj;
        const float* vp;
        if (kp2 < S_ - Q_) {
            int page = pidx[b * P_ + kp2 / PS_];
            vp = kvc + ((((size_t)page * 2 + 1) * PS_ + (kp2 % PS_)) * NKV_ + kv) * HD_;
        } else {
            vp = qkv + (size_t)(b * Q_ + kp2 - (S_ - Q_)) * QKVD + (NQ_ + NKV_) * HD_ + kv * HD_;
        }
        acc += sc[jj] * vp[d];
    }
    vr[half][d] = acc;
    __syncthreads();
    if (tid < HD_)
        attn[(size_t)t * (NQ_ * HD_) + h * HD_ + tid] = (vr[0][tid] + vr[1][tid]) / denom;
}

// ---------------- router: logits, top-2, softmax weights ----------------
__global__ void router_kernel(const float* __restrict__ x2,
                              const float* __restrict__ wr,
                              const float* __restrict__ br,
                              int* __restrict__ eidx, float* __restrict__ ewt) {
    int t = blockIdx.x;
    int lane = threadIdx.x;
    float acc[E_] = {};
    for (int h = lane; h < H_; h += 32) {
        float xv = x2[(size_t)t * H_ + h];
        #pragma unroll
        for (int e = 0; e < E_; e++) acc[e] += xv * wr[h * E_ + e];
    }
    #pragma unroll
    for (int e = 0; e < E_; e++) {
        #pragma unroll
        for (int o = 16; o > 0; o >>= 1)
            acc[e] += __shfl_xor_sync(0xffffffffu, acc[e], o);
    }
    if (lane == 0) {
        float l[E_];
        #pragma unroll
        for (int e = 0; e < E_; e++) l[e] = acc[e] + br[e];
        int i0 = 0; float v0 = l[0];
        #pragma unroll
        for (int e = 1; e < E_; e++) if (l[e] > v0) { v0 = l[e]; i0 = e; }
        int i1 = -1; float v1 = -1e30f;
        #pragma unroll
        for (int e = 0; e < E_; e++)
            if (e != i0 && l[e] > v1) { v1 = l[e]; i1 = e; }
        float e1 = expf(v1 - v0);
        float inv = 1.f / (1.f + e1);
        eidx[t * 2 + 0] = i0; eidx[t * 2 + 1] = i1;
        ewt[t * 2 + 0] = inv; ewt[t * 2 + 1] = e1 * inv;
    }
}

// ---------------- fused MoE: top-2 experts per token, out += moe ----------------
// grid (T), 256 threads. Each block runs both experts sequentially.
__global__ void moe_kernel(const float* __restrict__ x2,
                           const int* __restrict__ eidx, const float* __restrict__ ewt,
                           const float* __restrict__ wgu, const float* __restrict__ bgu,
                           const float* __restrict__ wd, const float* __restrict__ bd,
                           float* __restrict__ out) {
    int t = blockIdx.x;
    int tid = threadIdx.x;
    __shared__ float xs[H_];
    __shared__ float act[FFN_];
    for (int i = tid; i < H_; i += 256) xs[i] = x2[(size_t)t * H_ + i];
    float outacc[4] = {};
    __syncthreads();

    for (int ei = 0; ei < 2; ei++) {
        int e = eidx[t * 2 + ei];
        float w = ewt[t * 2 + ei];
        const float* Wg = wgu + (size_t)e * H_ * (2 * FFN_);
        float ag[4] = {}, au[4] = {};
        for (int h = 0; h < H_; h++) {
            float xv = xs[h];
            const float* row = Wg + (size_t)h * (2 * FFN_);
            #pragma unroll
            for (int j = 0; j < 4; j++) {
                int f = tid + 256 * j;
                float2 gu = *(const float2*)&row[2 * f];
                ag[j] += xv * gu.x;
                au[j] += xv * gu.y;
            }
        }
        #pragma unroll
        for (int j = 0; j < 4; j++) {
            int f = tid + 256 * j;
            float g = ag[j] + bgu[(size_t)e * (2 * FFN_) + 2 * f];
            float u = au[j] + bgu[(size_t)e * (2 * FFN_) + 2 * f + 1];
            g = fminf(g, LIMIT_);
            u = fminf(fmaxf(u, -LIMIT_), LIMIT_);
            float glu = g / (1.f + expf(-g * ALPHA_));
            act[f] = (u + 1.f) * glu;
        }
        __syncthreads();

        const float* Wd = wd + (size_t)e * FFN_ * H_;
        float ad[4] = {};
        for (int f = 0; f < FFN_; f++) {
            float av = act[f];
            const float* row = Wd + (size_t)f * H_;
            #pragma unroll
            for (int j = 0; j < 4; j++) ad[j] += av * row[tid + 256 * j];
        }
        #pragma unroll
        for (int j = 0; j < 4; j++)
            outacc[j] += w * (ad[j] + bd[(size_t)e * H_ + tid + 256 * j]);
        __syncthreads();   // act reused next expert
    }
    #pragma unroll
    for (int j = 0; j < 4; j++) {
        int c = tid + 256 * j;
        out[(size_t)t * H_ + c] += outacc[j];
    }
}

// ---------------- launch ----------------
extern "C" void kernel_launch(void* const* d_in, const int* in_sizes, int n_in,
                              void* d_out, int out_size) {
    const float* hidden = (const float*)d_in[0];
    const float* kvc    = (const float*)d_in[1];
    const float* mask   = (const float*)d_in[2];
    const int*   pidx   = (const int*)d_in[3];
    const float* sinks  = (const float*)d_in[4];
    const float* w_qkv  = (const float*)d_in[5];
    const float* b_qkv  = (const float*)d_in[6];
    const float* w_o    = (const float*)d_in[7];
    const float* b_o    = (const float*)d_in[8];
    const float* ln1    = (const float*)d_in[9];
    const float* ln2    = (const float*)d_in[10];
    const float* w_r    = (const float*)d_in[11];
    const float* b_r    = (const float*)d_in[12];
    const float* w_gu   = (const float*)d_in[13];
    const float* b_gu   = (const float*)d_in[14];
    const float* w_d    = (const float*)d_in[15];
    const float* b_d    = (const float*)d_in[16];
    float* out = (float*)d_out;

    float *px, *pqkv, *pattn, *px2, *pewt; int* peidx;
    cudaGetSymbolAddress((void**)&px,    g_x);
    cudaGetSymbolAddress((void**)&pqkv,  g_qkv);
    cudaGetSymbolAddress((void**)&pattn, g_attn);
    cudaGetSymbolAddress((void**)&px2,   g_x2);
    cudaGetSymbolAddress((void**)&peidx, g_eidx);
    cudaGetSymbolAddress((void**)&pewt,  g_ewt);

    rmsnorm_kernel<<<T_, 256>>>(hidden, ln1, px);
    sgemm64<false><<<dim3(QKVD / 64, T_ / 64), 256>>>(px, w_qkv, b_qkv, nullptr,
                                                      pqkv, T_, QKVD, H_);
    attn_kernel<<<dim3(NQ_, Q_, B_), 128>>>(pqkv, kvc, pidx, mask, sinks, pattn);
    sgemm64<true><<<dim3(H_ / 64, T_ / 64), 256>>>(pattn, w_o, b_o, hidden,
                                                   out, T_, H_, H_);
    rmsnorm_kernel<<<T_, 256>>>(out, ln2, px2);
    router_kernel<<<T_, 32>>>(px2, w_r, b_r, peidx, pewt);
    moe_kernel<<<T_, 256>>>(px2, peidx, pewt, w_gu, b_gu, w_d, b_d, out);
}

// round 2
// speedup vs baseline: 2.0614x; 2.0614x over previous
#include <cuda_runtime.h>
#include <math.h>

#define T_    512
#define H_    1024
#define HD_   64
#define NQ_   16
#define NKV_  4
#define G_    4
#define E_    8
#define FFN_  1024
#define B_    4
#define Q_    128
#define P_    8
#define PS_   128
#define S_    1024
#define SW_   128
#define QKVD  1536
#define SCALE_ 0.125f
#define ALPHA_ 1.702f
#define LIMIT_ 7.0f
#define EPS_   1e-5f
#define NAPAD 2048          // max padded assignment slots (1024 + 8*127, rounded)

// ---------------- scratch ----------------
__device__ float g_x[T_ * H_];
__device__ float g_qkv[T_ * QKVD];
__device__ float g_attn[T_ * NQ_ * HD_];
__device__ float g_x2[T_ * H_];
__device__ int   g_eidx[T_ * 2];
__device__ float g_ewt[T_ * 2];
__device__ int   g_eoff[E_];      // padded start slot per expert
__device__ int   g_ecnt[E_];      // actual count per expert
__device__ int   g_tokof[NAPAD];  // slot -> assignment id (t*2+ei), -1 = pad
__device__ int   g_slotmap[T_ * 2];
__device__ float g_xg[NAPAD * H_];
__device__ float g_act[NAPAD * FFN_];
__device__ float g_eo[NAPAD * H_];

// ---------------- rmsnorm ----------------
__global__ void rmsnorm_kernel(const float* __restrict__ in,
                               const float* __restrict__ w,
                               float* __restrict__ out) {
    int t = blockIdx.x;
    const float* x = in + (size_t)t * H_;
    __shared__ float red[256];
    float ss = 0.f;
    for (int i = threadIdx.x; i < H_; i += 256) { float v = x[i]; ss += v * v; }
    red[threadIdx.x] = ss; __syncthreads();
    for (int s = 128; s > 0; s >>= 1) {
        if (threadIdx.x < s) red[threadIdx.x] += red[threadIdx.x + s];
        __syncthreads();
    }
    float r = rsqrtf(red[0] / (float)H_ + EPS_);
    for (int i = threadIdx.x; i < H_; i += 256)
        out[(size_t)t * H_ + i] = x[i] * w[i] * r;
}

// ---------------- 64x64 register-tiled SGEMM (qkv / o-proj) ----------------
template<bool RES>
__global__ void sgemm64(const float* __restrict__ A, const float* __restrict__ B,
                        const float* __restrict__ bias, const float* __restrict__ res,
                        float* __restrict__ C, int M, int N, int K) {
    __shared__ float As[16][64];
    __shared__ float Bs[16][64];
    int tid = threadIdx.x;
    int tx = tid % 16, ty = tid / 16;
    int m0 = blockIdx.y * 64, n0 = blockIdx.x * 64;
    int arow = tid >> 2, ac4 = tid & 3;
    int brow = tid >> 4, bc4 = tid & 15;
    float acc[4][4] = {};
    for (int k0 = 0; k0 < K; k0 += 16) {
        float4 av = *(const float4*)&A[(size_t)(m0 + arow) * K + k0 + ac4 * 4];
        As[ac4 * 4 + 0][arow] = av.x;
        As[ac4 * 4 + 1][arow] = av.y;
        As[ac4 * 4 + 2][arow] = av.z;
        As[ac4 * 4 + 3][arow] = av.w;
        float4 bv = *(const float4*)&B[(size_t)(k0 + brow) * N + n0 + bc4 * 4];
        *(float4*)&Bs[brow][bc4 * 4] = bv;
        __syncthreads();
        #pragma unroll
        for (int k = 0; k < 16; k++) {
            float a[4], b[4];
            #pragma unroll
            for (int i = 0; i < 4; i++) a[i] = As[k][ty * 4 + i];
            #pragma unroll
            for (int j = 0; j < 4; j++) b[j] = Bs[k][tx * 4 + j];
            #pragma unroll
            for (int i = 0; i < 4; i++)
                #pragma unroll
                for (int j = 0; j < 4; j++)
                    acc[i][j] += a[i] * b[j];
        }
        __syncthreads();
    }
    #pragma unroll
    for (int i = 0; i < 4; i++) {
        int row = m0 + ty * 4 + i;
        #pragma unroll
        for (int j = 0; j < 4; j++) {
            int col = n0 + tx * 4 + j;
            float v = acc[i][j] + bias[col];
            if (RES) v += res[(size_t)row * N + col];
            C[(size_t)row * N + col] = v;
        }
    }
}

// ---------------- sliding-window attention with sink ----------------
__global__ void attn_kernel(const float* __restrict__ qkv,
                            const float* __restrict__ kvc,
                            const int* __restrict__ pidx,
                            const float* __restrict__ mask,
                            const float* __restrict__ sinks,
                            float* __restrict__ attn) {
    int h = blockIdx.x, q = blockIdx.y, b = blockIdx.z;
    int t = b * Q_ + q;
    int qpos = S_ - Q_ + q;
    int kv = h / G_;
    int tid = threadIdx.x;

    __shared__ float qs[HD_];
    __shared__ float sc[SW_];
    __shared__ float red[SW_];
    __shared__ float vr[2][HD_];

    if (tid < HD_) qs[tid] = qkv[(size_t)t * QKVD + h * HD_ + tid] * SCALE_;
    __syncthreads();

    int kpos = qpos - (SW_ - 1) + tid;
    const float* kp;
    if (kpos < S_ - Q_) {
        int page = pidx[b * P_ + kpos / PS_];
        kp = kvc + ((((size_t)page * 2 + 0) * PS_ + (kpos % PS_)) * NKV_ + kv) * HD_;
    } else {
        kp = qkv + (size_t)(b * Q_ + kpos - (S_ - Q_)) * QKVD + NQ_ * HD_ + kv * HD_;
    }
    float s = 0.f;
    #pragma unroll
    for (int d = 0; d < HD_; d++) s += qs[d] * kp[d];
    s += mask[((size_t)b * Q_ + q) * S_ + kpos];
    sc[tid] = s;
    red[tid] = s;
    __syncthreads();
    for (int st = 64; st > 0; st >>= 1) {
        if (tid < st) red[tid] = fmaxf(red[tid], red[tid + st]);
        __syncthreads();
    }
    float m = red[0];
    __syncthreads();
    float p = expf(s - m);
    sc[tid] = p;
    red[tid] = p;
    __syncthreads();
    for (int st = 64; st > 0; st >>= 1) {
        if (tid < st) red[tid] += red[tid + st];
        __syncthreads();
    }
    float denom = red[0] + expf(sinks[h] - m);

    int half = tid >> 6;
    int d = tid & 63;
    float acc = 0.f;
    for (int jj = half * 64; jj < half * 64 + 64; jj++) {
        int kp2 = qpos - (SW_ - 1) + jj;
        const float* vp;
        if (kp2 < S_ - Q_) {
            int page = pidx[b * P_ + kp2 / PS_];
            vp = kvc + ((((size_t)page * 2 + 1) * PS_ + (kp2 % PS_)) * NKV_ + kv) * HD_;
        } else {
            vp = qkv + (size_t)(b * Q_ + kp2 - (S_ - Q_)) * QKVD + (NQ_ + NKV_) * HD_ + kv * HD_;
        }
        acc += sc[jj] * vp[d];
    }
    vr[half][d] = acc;
    __syncthreads();
    if (tid < HD_)
        attn[(size_t)t * (NQ_ * HD_) + h * HD_ + tid] = (vr[0][tid] + vr[1][tid]) / denom;
}

// ---------------- router ----------------
__global__ void router_kernel(const float* __restrict__ x2,
                              const float* __restrict__ wr,
                              const float* __restrict__ br,
                              int* __restrict__ eidx, float* __restrict__ ewt) {
    int t = blockIdx.x;
    int lane = threadIdx.x;
    float acc[E_] = {};
    for (int h = lane; h < H_; h += 32) {
        float xv = x2[(size_t)t * H_ + h];
        #pragma unroll
        for (int e = 0; e < E_; e++) acc[e] += xv * wr[h * E_ + e];
    }
    #pragma unroll
    for (int e = 0; e < E_; e++) {
        #pragma unroll
        for (int o = 16; o > 0; o >>= 1)
            acc[e] += __shfl_xor_sync(0xffffffffu, acc[e], o);
    }
    if (lane == 0) {
        float l[E_];
        #pragma unroll
        for (int e = 0; e < E_; e++) l[e] = acc[e] + br[e];
        int i0 = 0; float v0 = l[0];
        #pragma unroll
        for (int e = 1; e < E_; e++) if (l[e] > v0) { v0 = l[e]; i0 = e; }
        int i1 = -1; float v1 = -1e30f;
        #pragma unroll
        for (int e = 0; e < E_; e++)
            if (e != i0 && l[e] > v1) { v1 = l[e]; i1 = e; }
        float e1 = expf(v1 - v0);
        float inv = 1.f / (1.f + e1);
        eidx[t * 2 + 0] = i0; eidx[t * 2 + 1] = i1;
        ewt[t * 2 + 0] = inv; ewt[t * 2 + 1] = e1 * inv;
    }
}

// ---------------- route sort: per-expert contiguous slots, padded to 128 ----------------
__global__ void route_sort_kernel(const int* __restrict__ eidx,
                                  int* __restrict__ eoff, int* __restrict__ ecnt,
                                  int* __restrict__ tokof, int* __restrict__ slotmap) {
    __shared__ int cnt[E_];
    __shared__ int pos[E_];
    int tid = threadIdx.x;
    if (tid < E_) cnt[tid] = 0;
    for (int i = tid; i < NAPAD; i += 256) tokof[i] = -1;
    __syncthreads();
    for (int a = tid; a < T_ * 2; a += 256) atomicAdd(&cnt[eidx[a]], 1);
    __syncthreads();
    if (tid == 0) {
        int off = 0;
        for (int e = 0; e < E_; e++) {
            eoff[e] = off; ecnt[e] = cnt[e]; pos[e] = off;
            off += ((cnt[e] + 127) / 128) * 128;
        }
    }
    __syncthreads();
    for (int a = tid; a < T_ * 2; a += 256) {
        int e = eidx[a];
        int slot = atomicAdd(&pos[e], 1);
        tokof[slot] = a;
        slotmap[a] = slot;
    }
}

// ---------------- gather x2 -> per-slot rows (zero padding) ----------------
__global__ void gather_kernel(const float* __restrict__ x2,
                              const int* __restrict__ tokof,
                              float* __restrict__ xg) {
    int slot = blockIdx.x;
    int a = tokof[slot];
    float4* dst = (float4*)(xg + (size_t)slot * H_);
    if (a < 0) {
        dst[threadIdx.x] = make_float4(0.f, 0.f, 0.f, 0.f);
    } else {
        const float4* src = (const float4*)(x2 + (size_t)(a >> 1) * H_);
        dst[threadIdx.x] = src[threadIdx.x];
    }
}

// ---------------- 128x64 SGEMM body (shared by both MoE GEMMs) ----------------
// A rows are global slot rows; thread layout: ty=tid/16 over M (8 rows), tx=tid%16 over N (4 cols)
__device__ __forceinline__ void gemm128x64_body(
    const float* __restrict__ A, const float* __restrict__ Bw,
    int m0, int n0, int K, int ldb, float acc[8][4],
    float As[16][136], float Bs[16][64]) {
    int tid = threadIdx.x;
    int ty = tid >> 4, tx = tid & 15;
    int brow = tid >> 4, bc4 = tid & 15;
    for (int k0 = 0; k0 < K; k0 += 16) {
        #pragma unroll
        for (int l = 0; l < 2; l++) {
            int f4 = tid * 2 + l;
            int row = f4 >> 2, c4 = f4 & 3;
            float4 av = *(const float4*)&A[(size_t)(m0 + row) * K + k0 + c4 * 4];
            As[c4 * 4 + 0][row] = av.x;
            As[c4 * 4 + 1][row] = av.y;
            As[c4 * 4 + 2][row] = av.z;
            As[c4 * 4 + 3][row] = av.w;
        }
        float4 bv = *(const float4*)&Bw[(size_t)(k0 + brow) * ldb + n0 + bc4 * 4];
        *(float4*)&Bs[brow][bc4 * 4] = bv;
        __syncthreads();
        #pragma unroll
        for (int k = 0; k < 16; k++) {
            float4 a0 = *(float4*)&As[k][ty * 8];
            float4 a1 = *(float4*)&As[k][ty * 8 + 4];
            float4 b  = *(float4*)&Bs[k][tx * 4];
            float a[8] = {a0.x, a0.y, a0.z, a0.w, a1.x, a1.y, a1.z, a1.w};
            float bb[4] = {b.x, b.y, b.z, b.w};
            #pragma unroll
            for (int i = 0; i < 8; i++)
                #pragma unroll
                for (int j = 0; j < 4; j++)
                    acc[i][j] += a[i] * bb[j];
        }
        __syncthreads();
    }
}

// ---------------- MoE gate_up GEMM + fused swiglu ----------------
__global__ __launch_bounds__(256) void moe_gu_kernel(
    const float* __restrict__ xg, const float* __restrict__ wgu,
    const float* __restrict__ bgu,
    const int* __restrict__ eoff, const int* __restrict__ ecnt,
    float* __restrict__ act) {
    int e = blockIdx.z;
    if ((int)blockIdx.y * 128 >= ecnt[e]) return;
    int m0 = eoff[e] + blockIdx.y * 128;
    int n0 = blockIdx.x * 64;
    const float* Bw = wgu + (size_t)e * H_ * (2 * FFN_);
    __shared__ float As[16][136];
    __shared__ float Bs[16][64];
    float acc[8][4] = {};
    gemm128x64_body(xg, Bw, m0, n0, H_, 2 * FFN_, acc, As, Bs);
    int ty = threadIdx.x >> 4, tx = threadIdx.x & 15;
    #pragma unroll
    for (int i = 0; i < 8; i++) {
        int row = m0 + ty * 8 + i;
        #pragma unroll
        for (int j = 0; j < 4; j += 2) {
            int col = n0 + tx * 4 + j;           // even: gate, odd: up
            float g = acc[i][j]     + bgu[(size_t)e * (2 * FFN_) + col];
            float u = acc[i][j + 1] + bgu[(size_t)e * (2 * FFN_) + col + 1];
            g = fminf(g, LIMIT_);
            u = fminf(fmaxf(u, -LIMIT_), LIMIT_);
            float glu = g / (1.f + expf(-g * ALPHA_));
            act[(size_t)row * FFN_ + (col >> 1)] = (u + 1.f) * glu;
        }
    }
}

// ---------------- MoE down GEMM + bias ----------------
__global__ __launch_bounds__(256) void moe_down_kernel(
    const float* __restrict__ act, const float* __restrict__ wd,
    const float* __restrict__ bd,
    const int* __restrict__ eoff, const int* __restrict__ ecnt,
    float* __restrict__ eo) {
    int e = blockIdx.z;
    if ((int)blockIdx.y * 128 >= ecnt[e]) return;
    int m0 = eoff[e] + blockIdx.y * 128;
    int n0 = blockIdx.x * 64;
    const float* Bw = wd + (size_t)e * FFN_ * H_;
    __shared__ float As[16][136];
    __shared__ float Bs[16][64];
    float acc[8][4] = {};
    gemm128x64_body(act, Bw, m0, n0, FFN_, H_, acc, As, Bs);
    int ty = threadIdx.x >> 4, tx = threadIdx.x & 15;
    #pragma unroll
    for (int i = 0; i < 8; i++) {
        int row = m0 + ty * 8 + i;
        #pragma unroll
        for (int j = 0; j < 4; j++) {
            int col = n0 + tx * 4 + j;
            eo[(size_t)row * H_ + col] = acc[i][j] + bd[(size_t)e * H_ + col];
        }
    }
}

// ---------------- combine: out += w0*eo[slot0] + w1*eo[slot1] ----------------
__global__ void combine_kernel(const float* __restrict__ eo,
                               const int* __restrict__ slotmap,
                               const float* __restrict__ ewt,
                               float* __restrict__ out) {
    int t = blockIdx.x;
    int s0 = slotmap[t * 2 + 0], s1 = slotmap[t * 2 + 1];
    float w0 = ewt[t * 2 + 0], w1 = ewt[t * 2 + 1];
    const float4* e0 = (const float4*)(eo + (size_t)s0 * H_);
    const float4* e1 = (const float4*)(eo + (size_t)s1 * H_);
    float4* o = (float4*)(out + (size_t)t * H_);
    int i = threadIdx.x;
    float4 a = e0[i], b = e1[i], c = o[i];
    c.x += w0 * a.x + w1 * b.x;
    c.y += w0 * a.y + w1 * b.y;
    c.z += w0 * a.z + w1 * b.z;
    c.w += w0 * a.w + w1 * b.w;
    o[i] = c;
}

// ---------------- launch ----------------
extern "C" void kernel_launch(void* const* d_in, const int* in_sizes, int n_in,
                              void* d_out, int out_size) {
    const float* hidden = (const float*)d_in[0];
    const float* kvc    = (const float*)d_in[1];
    const float* mask   = (const float*)d_in[2];
    const int*   pidx   = (const int*)d_in[3];
    const float* sinks  = (const float*)d_in[4];
    const float* w_qkv  = (const float*)d_in[5];
    const float* b_qkv  = (const float*)d_in[6];
    const float* w_o    = (const float*)d_in[7];
    const float* b_o    = (const float*)d_in[8];
    const float* ln1    = (const float*)d_in[9];
    const float* ln2    = (const float*)d_in[10];
    const float* w_r    = (const float*)d_in[11];
    const float* b_r    = (const float*)d_in[12];
    const float* w_gu   = (const float*)d_in[13];
    const float* b_gu   = (const float*)d_in[14];
    const float* w_d    = (const float*)d_in[15];
    const float* b_d    = (const float*)d_in[16];
    float* out = (float*)d_out;

    float *px, *pqkv, *pattn, *px2, *pewt, *pxg, *pact, *peo;
    int *peidx, *peoff, *pecnt, *ptokof, *pslot;
    cudaGetSymbolAddress((void**)&px,     g_x);
    cudaGetSymbolAddress((void**)&pqkv,   g_qkv);
    cudaGetSymbolAddress((void**)&pattn,  g_attn);
    cudaGetSymbolAddress((void**)&px2,    g_x2);
    cudaGetSymbolAddress((void**)&peidx,  g_eidx);
    cudaGetSymbolAddress((void**)&pewt,   g_ewt);
    cudaGetSymbolAddress((void**)&peoff,  g_eoff);
    cudaGetSymbolAddress((void**)&pecnt,  g_ecnt);
    cudaGetSymbolAddress((void**)&ptokof, g_tokof);
    cudaGetSymbolAddress((void**)&pslot,  g_slotmap);
    cudaGetSymbolAddress((void**)&pxg,    g_xg);
    cudaGetSymbolAddress((void**)&pact,   g_act);
    cudaGetSymbolAddress((void**)&peo,    g_eo);

    rmsnorm_kernel<<<T_, 256>>>(hidden, ln1, px);
    sgemm64<false><<<dim3(QKVD / 64, T_ / 64), 256>>>(px, w_qkv, b_qkv, nullptr,
                                                      pqkv, T_, QKVD, H_);
    attn_kernel<<<dim3(NQ_, Q_, B_), 128>>>(pqkv, kvc, pidx, mask, sinks, pattn);
    sgemm64<true><<<dim3(H_ / 64, T_ / 64), 256>>>(pattn, w_o, b_o, hidden,
                                                   out, T_, H_, H_);
    rmsnorm_kernel<<<T_, 256>>>(out, ln2, px2);
    router_kernel<<<T_, 32>>>(px2, w_r, b_r, peidx, pewt);
    route_sort_kernel<<<1, 256>>>(peidx, peoff, pecnt, ptokof, pslot);
    gather_kernel<<<NAPAD, 256>>>(px2, ptokof, pxg);
    moe_gu_kernel<<<dim3(2 * FFN_ / 64, 4, E_), 256>>>(pxg, w_gu, b_gu,
                                                       peoff, pecnt, pact);
    moe_down_kernel<<<dim3(H_ / 64, 4, E_), 256>>>(pact, w_d, b_d,
                                                   peoff, pecnt, peo);
    combine_kernel<<<T_, 256>>>(peo, pslot, pewt, out);
}

// round 4
// speedup vs baseline: 3.0085x; 1.4594x over previous
#include <cuda_runtime.h>
#include <cstdint>
#include <math.h>

#define T_    512
#define H_    1024
#define HD_   64
#define NQ_   16
#define NKV_  4
#define G_    4
#define E_    8
#define FFN_  1024
#define B_    4
#define Q_    128
#define P_    8
#define PS_   128
#define S_    1024
#define SW_   128
#define QKVD  1536
#define SCALE_ 0.125f
#define ALPHA_ 1.702f
#define LIMIT_ 7.0f
#define EPS_   1e-5f
#define NAPAD 2048

// ---------------- scratch ----------------
__device__ float g_x[T_ * H_];
__device__ float g_qkv[T_ * QKVD];
__device__ float g_attn[T_ * NQ_ * HD_];
__device__ float g_x2[T_ * H_];
__device__ int   g_eidx[T_ * 2];
__device__ float g_ewt[T_ * 2];
__device__ int   g_eoff[E_];
__device__ int   g_ecnt[E_];
__device__ int   g_tokof[NAPAD];
__device__ int   g_slotmap[T_ * 2];
__device__ float g_xg[NAPAD * H_];
__device__ float g_act[NAPAD * FFN_];
__device__ float g_eo[NAPAD * H_];

// ---------------- rmsnorm ----------------
__global__ void rmsnorm_kernel(const float* __restrict__ in,
                               const float* __restrict__ w,
                               float* __restrict__ out) {
    int t = blockIdx.x;
    const float* x = in + (size_t)t * H_;
    __shared__ float red[256];
    float ss = 0.f;
    for (int i = threadIdx.x; i < H_; i += 256) { float v = x[i]; ss += v * v; }
    red[threadIdx.x] = ss; __syncthreads();
    for (int s = 128; s > 0; s >>= 1) {
        if (threadIdx.x < s) red[threadIdx.x] += red[threadIdx.x + s];
        __syncthreads();
    }
    float r = rsqrtf(red[0] / (float)H_ + EPS_);
    for (int i = threadIdx.x; i < H_; i += 256)
        out[(size_t)t * H_ + i] = x[i] * w[i] * r;
}

// ---------------- tf32 helpers ----------------
__device__ __forceinline__ uint32_t f2tf(float f) {
    uint32_t r; asm("cvt.rna.tf32.f32 %0, %1;" : "=r"(r) : "f"(f)); return r;
}
__device__ __forceinline__ void mma8(float* c, uint32_t a0, uint32_t a1,
                                     uint32_t a2, uint32_t a3,
                                     uint32_t b0, uint32_t b1) {
    asm volatile("mma.sync.aligned.m16n8k8.row.col.f32.tf32.tf32.f32 "
        "{%0,%1,%2,%3}, {%4,%5,%6,%7}, {%8,%9}, {%0,%1,%2,%3};"
        : "+f"(c[0]), "+f"(c[1]), "+f"(c[2]), "+f"(c[3])
        : "r"(a0), "r"(a1), "r"(a2), "r"(a3), "r"(b0), "r"(b1));
}

// ---------------- unified tf32 tensor-core GEMM ----------------
// C[M,N] = A[M,K] @ B[K,N] (+bias, epilogue per MODE)
// MODE 0: +bias           (qkv)
// MODE 1: +bias +res      (o-proj)
// MODE 2: swiglu -> act   (moe gate_up; expert-tiled)
// MODE 3: +bias -> eo     (moe down;    expert-tiled)
// Tile 128x128xBK16, 256 threads, warp grid 2(m) x 4(n), 64x32 per warp.
template<int MODE>
__global__ __launch_bounds__(256, 2) void gemm_tf32(
    const float* __restrict__ A, const float* __restrict__ Bw,
    const float* __restrict__ bias, const float* __restrict__ res,
    float* __restrict__ C, int K, int N,
    const int* __restrict__ eoff, const int* __restrict__ ecnt) {
    __shared__ uint32_t As[16][136];   // A^T tile, XOR-swizzled columns
    __shared__ uint32_t Bs[16][136];
    int tid = threadIdx.x, lane = tid & 31, wid = tid >> 5;
    int n0 = blockIdx.x * 128;
    int m0;
    if (MODE >= 2) {
        int e = blockIdx.z;
        if ((int)blockIdx.y * 128 >= ecnt[e]) return;
        m0 = eoff[e] + blockIdx.y * 128;
        Bw += (size_t)e * K * N;
        bias += (size_t)e * N;
    } else {
        m0 = blockIdx.y * 128;
    }
    int wm = (wid >> 2) * 64, wn = (wid & 3) * 32;

    float acc[16][4];
    #pragma unroll
    for (int i = 0; i < 16; i++)
        #pragma unroll
        for (int j = 0; j < 4; j++) acc[i][j] = 0.f;

    float4 av[2], bv[2];
    // preload chunk 0
    #pragma unroll
    for (int l = 0; l < 2; l++) {
        int fa = tid + 256 * l;
        av[l] = *(const float4*)&A[(size_t)(m0 + (fa >> 2)) * K + (fa & 3) * 4];
        bv[l] = *(const float4*)&Bw[(size_t)(fa >> 5) * N + n0 + (fa & 31) * 4];
    }
    int nchunks = K / 16;
    for (int c = 0; c < nchunks; c++) {
        // stage current chunk into smem (convert to tf32)
        #pragma unroll
        for (int l = 0; l < 2; l++) {
            int fa = tid + 256 * l;
            int arow = fa >> 2, ac = fa & 3;
            float v[4] = {av[l].x, av[l].y, av[l].z, av[l].w};
            #pragma unroll
            for (int i = 0; i < 4; i++) {
                int k = ac * 4 + i;
                As[k][arow ^ ((k >> 2) << 3)] = f2tf(v[i]);
            }
            int brow = fa >> 5, bc4 = fa & 31;
            uint4 u;
            u.x = f2tf(bv[l].x); u.y = f2tf(bv[l].y);
            u.z = f2tf(bv[l].z); u.w = f2tf(bv[l].w);
            *(uint4*)&Bs[brow][bc4 * 4] = u;
        }
        __syncthreads();
        // prefetch next chunk
        if (c + 1 < nchunks) {
            int k0 = (c + 1) * 16;
            #pragma unroll
            for (int l = 0; l < 2; l++) {
                int fa = tid + 256 * l;
                av[l] = *(const float4*)&A[(size_t)(m0 + (fa >> 2)) * K + k0 + (fa & 3) * 4];
                bv[l] = *(const float4*)&Bw[(size_t)(k0 + (fa >> 5)) * N + n0 + (fa & 31) * 4];
            }
        }
        // compute 2 k-steps of k=8
        #pragma unroll
        for (int ks = 0; ks < 2; ks++) {
            int kq = ks * 8 + (lane & 3);
            int x0 = ((kq) >> 2) << 3, x1 = ((kq + 4) >> 2) << 3;
            uint32_t b[4][2];
            #pragma unroll
            for (int ni = 0; ni < 4; ni++) {
                int n = wn + ni * 8 + (lane >> 2);
                b[ni][0] = Bs[kq][n];
                b[ni][1] = Bs[kq + 4][n];
            }
            #pragma unroll
            for (int mi = 0; mi < 4; mi++) {
                int m = wm + mi * 16 + (lane >> 2);
                uint32_t a0 = As[kq][m ^ x0];
                uint32_t a1 = As[kq][(m + 8) ^ x0];
                uint32_t a2 = As[kq + 4][m ^ x1];
                uint32_t a3 = As[kq + 4][(m + 8) ^ x1];
                #pragma unroll
                for (int ni = 0; ni < 4; ni++)
                    mma8(acc[mi * 4 + ni], a0, a1, a2, a3, b[ni][0], b[ni][1]);
            }
        }
        __syncthreads();
    }
    // epilogue
    #pragma unroll
    for (int mi = 0; mi < 4; mi++) {
        #pragma unroll
        for (int ni = 0; ni < 4; ni++) {
            float* cc = acc[mi * 4 + ni];
            int row = m0 + wm + mi * 16 + (lane >> 2);
            int col = n0 + wn + ni * 8 + 2 * (lane & 3);
            #pragma unroll
            for (int h = 0; h < 2; h++) {
                int r = row + h * 8;
                float v0 = cc[h * 2 + 0] + bias[col];
                float v1 = cc[h * 2 + 1] + bias[col + 1];
                if (MODE == 2) {
                    float g = fminf(v0, LIMIT_);
                    float u = fminf(fmaxf(v1, -LIMIT_), LIMIT_);
                    float glu = g / (1.f + expf(-g * ALPHA_));
                    C[(size_t)r * (N >> 1) + (col >> 1)] = (u + 1.f) * glu;
                } else {
                    if (MODE == 1) {
                        v0 += res[(size_t)r * N + col];
                        v1 += res[(size_t)r * N + col + 1];
                    }
                    *(float2*)&C[(size_t)r * N + col] = make_float2(v0, v1);
                }
            }
        }
    }
}

// ---------------- sliding-window attention with sink ----------------
__global__ void attn_kernel(const float* __restrict__ qkv,
                            const float* __restrict__ kvc,
                            const int* __restrict__ pidx,
                            const float* __restrict__ mask,
                            const float* __restrict__ sinks,
                            float* __restrict__ attn) {
    int h = blockIdx.x, q = blockIdx.y, b = blockIdx.z;
    int t = b * Q_ + q;
    int qpos = S_ - Q_ + q;
    int kv = h / G_;
    int tid = threadIdx.x;

    __shared__ float qs[HD_];
    __shared__ float sc[SW_];
    __shared__ float red[SW_];
    __shared__ float vr[2][HD_];

    if (tid < HD_) qs[tid] = qkv[(size_t)t * QKVD + h * HD_ + tid] * SCALE_;
    __syncthreads();

    int kpos = qpos - (SW_ - 1) + tid;
    const float* kp;
    if (kpos < S_ - Q_) {
        int page = pidx[b * P_ + kpos / PS_];
        kp = kvc + ((((size_t)page * 2 + 0) * PS_ + (kpos % PS_)) * NKV_ + kv) * HD_;
    } else {
        kp = qkv + (size_t)(b * Q_ + kpos - (S_ - Q_)) * QKVD + NQ_ * HD_ + kv * HD_;
    }
    float s = 0.f;
    #pragma unroll
    for (int d = 0; d < HD_; d++) s += qs[d] * kp[d];
    s += mask[((size_t)b * Q_ + q) * S_ + kpos];
    sc[tid] = s;
    red[tid] = s;
    __syncthreads();
    for (int st = 64; st > 0; st >>= 1) {
        if (tid < st) red[tid] = fmaxf(red[tid], red[tid + st]);
        __syncthreads();
    }
    float m = red[0];
    __syncthreads();
    float p = expf(s - m);
    sc[tid] = p;
    red[tid] = p;
    __syncthreads();
    for (int st = 64; st > 0; st >>= 1) {
        if (tid < st) red[tid] += red[tid + st];
        __syncthreads();
    }
    float denom = red[0] + expf(sinks[h] - m);

    int half = tid >> 6;
    int d = tid & 63;
    float acc = 0.f;
    for (int jj = half * 64; jj < half * 64 + 64; jj++) {
        int kp2 = qpos - (SW_ - 1) + jj;
        const float* vp;
        if (kp2 < S_ - Q_) {
            int page = pidx[b * P_ + kp2 / PS_];
            vp = kvc + ((((size_t)page * 2 + 1) * PS_ + (kp2 % PS_)) * NKV_ + kv) * HD_;
        } else {
            vp = qkv + (size_t)(b * Q_ + kp2 - (S_ - Q_)) * QKVD + (NQ_ + NKV_) * HD_ + kv * HD_;
        }
        acc += sc[jj] * vp[d];
    }
    vr[half][d] = acc;
    __syncthreads();
    if (tid < HD_)
        attn[(size_t)t * (NQ_ * HD_) + h * HD_ + tid] = (vr[0][tid] + vr[1][tid]) / denom;
}

// ---------------- router ----------------
__global__ void router_kernel(const float* __restrict__ x2,
                              const float* __restrict__ wr,
                              const float* __restrict__ br,
                              int* __restrict__ eidx, float* __restrict__ ewt) {
    int t = blockIdx.x;
    int lane = threadIdx.x;
    float acc[E_] = {};
    for (int h = lane; h < H_; h += 32) {
        float xv = x2[(size_t)t * H_ + h];
        #pragma unroll
        for (int e = 0; e < E_; e++) acc[e] += xv * wr[h * E_ + e];
    }
    #pragma unroll
    for (int e = 0; e < E_; e++) {
        #pragma unroll
        for (int o = 16; o > 0; o >>= 1)
            acc[e] += __shfl_xor_sync(0xffffffffu, acc[e], o);
    }
    if (lane == 0) {
        float l[E_];
        #pragma unroll
        for (int e = 0; e < E_; e++) l[e] = acc[e] + br[e];
        int i0 = 0; float v0 = l[0];
        #pragma unroll
        for (int e = 1; e < E_; e++) if (l[e] > v0) { v0 = l[e]; i0 = e; }
        int i1 = -1; float v1 = -1e30f;
        #pragma unroll
        for (int e = 0; e < E_; e++)
            if (e != i0 && l[e] > v1) { v1 = l[e]; i1 = e; }
        float e1 = expf(v1 - v0);
        float inv = 1.f / (1.f + e1);
        eidx[t * 2 + 0] = i0; eidx[t * 2 + 1] = i1;
        ewt[t * 2 + 0] = inv; ewt[t * 2 + 1] = e1 * inv;
    }
}

// ---------------- route sort ----------------
__global__ void route_sort_kernel(const int* __restrict__ eidx,
                                  int* __restrict__ eoff, int* __restrict__ ecnt,
                                  int* __restrict__ tokof, int* __restrict__ slotmap) {
    __shared__ int cnt[E_];
    __shared__ int pos[E_];
    int tid = threadIdx.x;
    if (tid < E_) cnt[tid] = 0;
    for (int i = tid; i < NAPAD; i += 256) tokof[i] = -1;
    __syncthreads();
    for (int a = tid; a < T_ * 2; a += 256) atomicAdd(&cnt[eidx[a]], 1);
    __syncthreads();
    if (tid == 0) {
        int off = 0;
        for (int e = 0; e < E_; e++) {
            eoff[e] = off; ecnt[e] = cnt[e]; pos[e] = off;
            off += ((cnt[e] + 127) / 128) * 128;
        }
    }
    __syncthreads();
    for (int a = tid; a < T_ * 2; a += 256) {
        int e = eidx[a];
        int slot = atomicAdd(&pos[e], 1);
        tokof[slot] = a;
        slotmap[a] = slot;
    }
}

// ---------------- gather ----------------
__global__ void gather_kernel(const float* __restrict__ x2,
                              const int* __restrict__ tokof,
                              float* __restrict__ xg) {
    int slot = blockIdx.x;
    int a = tokof[slot];
    float4* dst = (float4*)(xg + (size_t)slot * H_);
    if (a < 0) {
        dst[threadIdx.x] = make_float4(0.f, 0.f, 0.f, 0.f);
    } else {
        const float4* src = (const float4*)(x2 + (size_t)(a >> 1) * H_);
        dst[threadIdx.x] = src[threadIdx.x];
    }
}

// ---------------- combine ----------------
__global__ void combine_kernel(const float* __restrict__ eo,
                               const int* __restrict__ slotmap,
                               const float* __restrict__ ewt,
                               float* __restrict__ out) {
    int t = blockIdx.x;
    int s0 = slotmap[t * 2 + 0], s1 = slotmap[t * 2 + 1];
    float w0 = ewt[t * 2 + 0], w1 = ewt[t * 2 + 1];
    const float4* e0 = (const float4*)(eo + (size_t)s0 * H_);
    const float4* e1 = (const float4*)(eo + (size_t)s1 * H_);
    float4* o = (float4*)(out + (size_t)t * H_);
    int i = threadIdx.x;
    float4 a = e0[i], b = e1[i], c = o[i];
    c.x += w0 * a.x + w1 * b.x;
    c.y += w0 * a.y + w1 * b.y;
    c.z += w0 * a.z + w1 * b.z;
    c.w += w0 * a.w + w1 * b.w;
    o[i] = c;
}

// ---------------- launch ----------------
extern "C" void kernel_launch(void* const* d_in, const int* in_sizes, int n_in,
                              void* d_out, int out_size) {
    const float* hidden = (const float*)d_in[0];
    const float* kvc    = (const float*)d_in[1];
    const float* mask   = (const float*)d_in[2];
    const int*   pidx   = (const int*)d_in[3];
    const float* sinks  = (const float*)d_in[4];
    const float* w_qkv  = (const float*)d_in[5];
    const float* b_qkv  = (const float*)d_in[6];
    const float* w_o    = (const float*)d_in[7];
    const float* b_o    = (const float*)d_in[8];
    const float* ln1    = (const float*)d_in[9];
    const float* ln2    = (const float*)d_in[10];
    const float* w_r    = (const float*)d_in[11];
    const float* b_r    = (const float*)d_in[12];
    const float* w_gu   = (const float*)d_in[13];
    const float* b_gu   = (const float*)d_in[14];
    const float* w_d    = (const float*)d_in[15];
    const float* b_d    = (const float*)d_in[16];
    float* out = (float*)d_out;

    float *px, *pqkv, *pattn, *px2, *pewt, *pxg, *pact, *peo;
    int *peidx, *peoff, *pecnt, *ptokof, *pslot;
    cudaGetSymbolAddress((void**)&px,     g_x);
    cudaGetSymbolAddress((void**)&pqkv,   g_qkv);
    cudaGetSymbolAddress((void**)&pattn,  g_attn);
    cudaGetSymbolAddress((void**)&px2,    g_x2);
    cudaGetSymbolAddress((void**)&peidx,  g_eidx);
    cudaGetSymbolAddress((void**)&pewt,   g_ewt);
    cudaGetSymbolAddress((void**)&peoff,  g_eoff);
    cudaGetSymbolAddress((void**)&pecnt,  g_ecnt);
    cudaGetSymbolAddress((void**)&ptokof, g_tokof);
    cudaGetSymbolAddress((void**)&pslot,  g_slotmap);
    cudaGetSymbolAddress((void**)&pxg,    g_xg);
    cudaGetSymbolAddress((void**)&pact,   g_act);
    cudaGetSymbolAddress((void**)&peo,    g_eo);

    rmsnorm_kernel<<<T_, 256>>>(hidden, ln1, px);
    gemm_tf32<0><<<dim3(QKVD / 128, T_ / 128), 256>>>(px, w_qkv, b_qkv, nullptr,
                                                      pqkv, H_, QKVD, nullptr, nullptr);
    attn_kernel<<<dim3(NQ_, Q_, B_), 128>>>(pqkv, kvc, pidx, mask, sinks, pattn);
    gemm_tf32<1><<<dim3(H_ / 128, T_ / 128), 256>>>(pattn, w_o, b_o, hidden,
                                                    out, H_, H_, nullptr, nullptr);
    rmsnorm_kernel<<<T_, 256>>>(out, ln2, px2);
    router_kernel<<<T_, 32>>>(px2, w_r, b_r, peidx, pewt);
    route_sort_kernel<<<1, 256>>>(peidx, peoff, pecnt, ptokof, pslot);
    gather_kernel<<<NAPAD, 256>>>(px2, ptokof, pxg);
    gemm_tf32<2><<<dim3(2 * FFN_ / 128, 8, E_), 256>>>(pxg, w_gu, b_gu, nullptr,
                                                       pact, H_, 2 * FFN_, peoff, pecnt);
    gemm_tf32<3><<<dim3(H_ / 128, 8, E_), 256>>>(pact, w_d, b_d, nullptr,
                                                 peo, FFN_, H_, peoff, pecnt);
    combine_kernel<<<T_, 256>>>(peo, pslot, pewt, out);
}